// round 7
// baseline (speedup 1.0000x reference)
#include <cuda_runtime.h>
#include <cstdint>

#define TILE_E    64
#define KDIM      256
#define NDIM      64
#define THREADS   512
#define ROW_B     1040                    // bytes per edge row: 256 floats + 16B pad
#define A_BUF_B   (TILE_E * ROW_B)        // 66560
#define B_OFF     (2 * A_BUF_B)           // 133120
#define B_BYTES   65536
#define SMEM_TOTAL (B_OFF + B_BYTES)      // 198656

__device__ int g_idx_is32;   // 1 if edge_index is int32, 0 if int64

__device__ __forceinline__ unsigned sm2u32(const void* p) {
    unsigned a;
    asm("{ .reg .u64 t; cvta.to.shared.u64 t, %1; cvt.u32.u64 %0, t; }" : "=r"(a) : "l"(p));
    return a;
}
__device__ __forceinline__ unsigned f2tf32(float f) {
    unsigned r; asm("cvt.rna.tf32.f32 %0, %1;" : "=r"(r) : "f"(f)); return r;
}
__device__ __forceinline__ void cp16(unsigned dst, const void* src) {
    asm volatile("cp.async.cg.shared.global [%0], [%1], 16;" :: "r"(dst), "l"(src) : "memory");
}
#define CP_COMMIT() asm volatile("cp.async.commit_group;" ::: "memory")
#define CP_WAIT1()  asm volatile("cp.async.wait_group 1;" ::: "memory")

// D += A(16x8) * B(8x8), tf32 -> f32
__device__ __forceinline__ void mma_tf32(float* c, unsigned a0, unsigned a1,
                                         unsigned a2, unsigned a3,
                                         unsigned b0, unsigned b1) {
    asm volatile(
        "mma.sync.aligned.m16n8k8.row.col.f32.tf32.tf32.f32 "
        "{%0,%1,%2,%3}, {%4,%5,%6,%7}, {%8,%9}, {%0,%1,%2,%3};"
        : "+f"(c[0]), "+f"(c[1]), "+f"(c[2]), "+f"(c[3])
        : "r"(a0), "r"(a1), "r"(a2), "r"(a3), "r"(b0), "r"(b1));
}

// Probe: int64 ids < 2^31 have zero odd 32-bit words; int32 data has node ids there.
__global__ void probe_idx_dtype(const int* __restrict__ w, int n_words) {
    int any = 0;
    for (int i = threadIdx.x * 2 + 1; i < n_words && i < 8192; i += 64) any |= w[i];
    any = __any_sync(0xffffffffu, any != 0);
    if (threadIdx.x == 0) g_idx_is32 = any ? 1 : 0;
}

// Async gather of tile `tile` into xbuf: 512 threads, 8 LDGSTS.16 per thread.
__device__ __forceinline__ void issue_gather(const float* __restrict__ node_emb,
                                             const void* __restrict__ edge_index,
                                             int is32, unsigned xbuf,
                                             int tile, int E, int n_nodes, int tid)
{
    const int r    = tid >> 2;                  // 0..127 : (e, half)
    const int e    = r & (TILE_E - 1);
    const int half = r >> 6;
    const int sub  = tid & 3;                   // 32-float slab within the half
    int ge = tile * TILE_E + e;
    if (ge >= E) ge = E - 1;                    // duplicate-gather tail; output guarded
    long long node;
    if (is32) node = ((const int*)edge_index)[(long long)half * E + ge];
    else      node = ((const long long*)edge_index)[(long long)half * E + ge];
    if (node < 0) node = 0;
    if (node >= n_nodes) node = n_nodes - 1;

    const float* src = node_emb + node * 128 + sub * 32;
    unsigned     dst = xbuf + e * ROW_B + half * 512 + sub * 128;
    #pragma unroll
    for (int q = 0; q < 8; ++q)
        cp16(dst + q * 16, src + q * 4);
    CP_COMMIT();
}

__global__ __launch_bounds__(THREADS, 1)
void edge_mlp_mma2(const float* __restrict__ node_emb,
                   const void*  __restrict__ edge_index,
                   const float* __restrict__ W1,
                   const float* __restrict__ b1,
                   const float* __restrict__ W2,
                   const float* __restrict__ b2,
                   float* __restrict__ out,
                   int E, int n_nodes, int ntiles)
{
    extern __shared__ unsigned char sm[];
    __shared__ float sPart[4][TILE_E];

    const int tid  = threadIdx.x;
    const int wid  = tid >> 5;
    const int lane = tid & 31;
    const int mw   = wid & 3;        // m-warp: edges mw*16 .. mw*16+15
    const int nw   = wid >> 2;       // n-warp: cols  nw*16 .. nw*16+15
    const int g    = lane >> 2;      // group id 0..7
    const int t    = lane & 3;
    const int is32 = g_idx_is32;

    // ---- stage B = W1 in m16n8k8 fragment order, tf32 (once) ----
    // entry idx = ks*128 + nwi*32 + lane : uint4 = (b0_f0, b1_f0, b0_f1, b1_f1)
    // frag f covers cols nwi*16 + f*8 + g ; k = ks*8 + t (+4 for b1)
    #pragma unroll
    for (int i = 0; i < 8; ++i) {
        const int idx = tid + i * 512;            // 0..4095
        const int l   = idx & 31;
        const int nwi = (idx >> 5) & 3;
        const int ks  = idx >> 7;
        const int gg  = l >> 2, tt = l & 3;
        const int k0  = ks * 8 + tt;
        const int n0  = nwi * 16 + gg;
        uint4 v;
        v.x = f2tf32(W1[k0 * NDIM + n0]);
        v.y = f2tf32(W1[(k0 + 4) * NDIM + n0]);
        v.z = f2tf32(W1[k0 * NDIM + n0 + 8]);
        v.w = f2tf32(W1[(k0 + 4) * NDIM + n0 + 8]);
        *(uint4*)(sm + B_OFF + idx * 16) = v;
    }

    // ---- per-thread epilogue constants: f=0,1 -> cols j0 = nw*16 + f*8 + 2t ----
    float b1a[2], w2a[2], b1b[2], w2b[2];
    #pragma unroll
    for (int f = 0; f < 2; ++f) {
        const int j0 = nw * 16 + f * 8 + 2 * t;
        b1a[f] = b1[j0];     w2a[f] = W2[j0];
        b1b[f] = b1[j0 + 1]; w2b[f] = W2[j0 + 1];
    }
    const float bb = b2[0];

    const unsigned x_u32[2] = { sm2u32(sm), sm2u32(sm + A_BUF_B) };
    const unsigned char* a0base = sm + (mw * 16 + g) * ROW_B + t * 4;  // row g, k-byte t*4
    const unsigned char* bP     = sm + B_OFF + nw * 512 + lane * 16;

    int tile = blockIdx.x;
    if (tile < ntiles)
        issue_gather(node_emb, edge_index, is32, x_u32[0], tile, E, n_nodes, tid);
    __syncthreads();   // B staged + prologue ordering

    int cur = 0;
    for (; tile < ntiles; tile += gridDim.x, cur ^= 1) {
        const int tn = tile + gridDim.x;
        if (tn < ntiles)
            issue_gather(node_emb, edge_index, is32, x_u32[cur ^ 1], tn, E, n_nodes, tid);
        else
            CP_COMMIT();
        CP_WAIT1();                  // current tile's gather complete
        __syncthreads();

        // ---- GEMM: warp m16 x n16, K=256 in 32 k8-steps ----
        float acc[2][4];
        #pragma unroll
        for (int f = 0; f < 2; ++f)
            #pragma unroll
            for (int c = 0; c < 4; ++c) acc[f][c] = 0.f;

        const unsigned char* aR0 = a0base + cur * A_BUF_B;
        const unsigned char* aR1 = aR0 + 8 * ROW_B;
        #pragma unroll 4
        for (int ks = 0; ks < KDIM / 8; ++ks) {
            const unsigned a0 = *(const unsigned*)(aR0 + ks * 32);
            const unsigned a2 = *(const unsigned*)(aR0 + ks * 32 + 16);
            const unsigned a1 = *(const unsigned*)(aR1 + ks * 32);
            const unsigned a3 = *(const unsigned*)(aR1 + ks * 32 + 16);
            const uint4 B0 = *(const uint4*)(bP + ks * 2048);
            mma_tf32(acc[0], a0, a1, a2, a3, B0.x, B0.y);
            mma_tf32(acc[1], a0, a1, a2, a3, B0.z, B0.w);
        }

        // ---- epilogue: relu(+b1) . W2, reduce over t-lanes, combine 4 n-warps ----
        float pg = 0.f, pg8 = 0.f;
        #pragma unroll
        for (int f = 0; f < 2; ++f) {
            pg  = fmaf(fmaxf(acc[f][0] + b1a[f], 0.f), w2a[f], pg);
            pg  = fmaf(fmaxf(acc[f][1] + b1b[f], 0.f), w2b[f], pg);
            pg8 = fmaf(fmaxf(acc[f][2] + b1a[f], 0.f), w2a[f], pg8);
            pg8 = fmaf(fmaxf(acc[f][3] + b1b[f], 0.f), w2b[f], pg8);
        }
        pg  += __shfl_xor_sync(0xffffffffu, pg, 1);
        pg  += __shfl_xor_sync(0xffffffffu, pg, 2);
        pg8 += __shfl_xor_sync(0xffffffffu, pg8, 1);
        pg8 += __shfl_xor_sync(0xffffffffu, pg8, 2);
        if (t == 0) {
            sPart[nw][mw * 16 + g]     = pg;
            sPart[nw][mw * 16 + g + 8] = pg8;
        }
        __syncthreads();
        if (tid < TILE_E) {
            const int e = tile * TILE_E + tid;
            if (e < E)
                out[e] = sPart[0][tid] + sPart[1][tid] + sPart[2][tid] + sPart[3][tid] + bb;
        }
        __syncthreads();   // sPart consumed + all A-buffer reads done before refill
    }
}

extern "C" void kernel_launch(void* const* d_in, const int* in_sizes, int n_in,
                              void* d_out, int out_size)
{
    const float* node_emb   = (const float*)d_in[0];
    const void*  edge_index = d_in[1];
    const float* W1         = (const float*)d_in[2];
    const float* b1         = (const float*)d_in[3];
    const float* W2         = (const float*)d_in[4];
    const float* b2         = (const float*)d_in[5];
    float*       out        = (float*)d_out;

    const int E       = out_size;
    const int n_nodes = in_sizes[0] / 128;
    const int ntiles  = (E + TILE_E - 1) / TILE_E;   // 12500

    probe_idx_dtype<<<1, 32>>>((const int*)edge_index, 2 * E);

    int nsm = 148;
    cudaDeviceGetAttribute(&nsm, cudaDevAttrMultiProcessorCount, 0);
    const int grid = nsm < ntiles ? nsm : ntiles;

    cudaFuncSetAttribute(edge_mlp_mma2,
                         cudaFuncAttributeMaxDynamicSharedMemorySize, SMEM_TOTAL);

    edge_mlp_mma2<<<grid, THREADS, SMEM_TOTAL>>>(node_emb, edge_index, W1, b1, W2, b2,
                                                 out, E, n_nodes, ntiles);
}

// round 8
// speedup vs baseline: 1.2512x; 1.2512x over previous
#include <cuda_runtime.h>
#include <cuda_fp16.h>
#include <cstdint>

#define TILE_E    64
#define KDIM      256
#define NDIM      64
#define THREADS   256
#define A_ROW_B   512                 // 256 halves per edge row
#define A_BYTES   (TILE_E * A_ROW_B)  // 32768
#define B_OFF     A_BYTES
#define B_BYTES   32768
#define SMEM_TOTAL (A_BYTES + B_BYTES)  // 65536 -> 3 CTAs/SM

__device__ int g_idx_is32;   // 1 if edge_index is int32, 0 if int64

__device__ __forceinline__ unsigned sm2u32(const void* p) {
    unsigned a;
    asm("{ .reg .u64 t; cvta.to.shared.u64 t, %1; cvt.u32.u64 %0, t; }" : "=r"(a) : "l"(p));
    return a;
}
__device__ __forceinline__ unsigned pkh2(float a, float b) {   // lo=a, hi=b
    __half2 h = __floats2half2_rn(a, b);
    return *(unsigned*)&h;
}
__device__ __forceinline__ void ldm_x4(unsigned& a0, unsigned& a1, unsigned& a2,
                                       unsigned& a3, unsigned addr) {
    asm volatile("ldmatrix.sync.aligned.m8n8.x4.shared.b16 {%0,%1,%2,%3}, [%4];"
                 : "=r"(a0), "=r"(a1), "=r"(a2), "=r"(a3) : "r"(addr));
}
__device__ __forceinline__ void mma16816(float* c, unsigned a0, unsigned a1,
                                         unsigned a2, unsigned a3,
                                         unsigned b0, unsigned b1) {
    asm volatile(
        "mma.sync.aligned.m16n8k16.row.col.f32.f16.f16.f32 "
        "{%0,%1,%2,%3}, {%4,%5,%6,%7}, {%8,%9}, {%0,%1,%2,%3};"
        : "+f"(c[0]), "+f"(c[1]), "+f"(c[2]), "+f"(c[3])
        : "r"(a0), "r"(a1), "r"(a2), "r"(a3), "r"(b0), "r"(b1));
}

// Probe: int64 ids < 2^31 have zero odd 32-bit words; int32 data has node ids there.
__global__ void probe_idx_dtype(const int* __restrict__ w, int n_words) {
    int any = 0;
    for (int i = threadIdx.x * 2 + 1; i < n_words && i < 8192; i += 64) any |= w[i];
    any = __any_sync(0xffffffffu, any != 0);
    if (threadIdx.x == 0) g_idx_is32 = any ? 1 : 0;
}

__global__ __launch_bounds__(THREADS, 3)
void edge_mlp_h16(const float* __restrict__ node_emb,
                  const void*  __restrict__ edge_index,
                  const float* __restrict__ W1,
                  const float* __restrict__ b1,
                  const float* __restrict__ W2,
                  const float* __restrict__ b2,
                  float* __restrict__ out,
                  int E, int n_nodes, int ntiles)
{
    extern __shared__ unsigned char sm[];
    __shared__ float sPart[2][TILE_E];

    const int tid  = threadIdx.x;
    const int wid  = tid >> 5;
    const int lane = tid & 31;
    const int mw   = wid & 3;        // m-warp: edges mw*16..+15
    const int nw   = wid >> 2;       // n-warp: cols  nw*32..+31
    const int g    = lane >> 2;
    const int t    = lane & 3;
    const int is32 = g_idx_is32;

    // ---- stage B = W1 as fp16 fragments (once) ----
    // entry idx=(w, nwi, p, lane): uint4 = frags 2p,2p+1: (b0,b1, b0',b1')
    // frag f covers cols nwi*32+f*8+g ; b0 = {W1[k0],W1[k0+1]}, k0=16w+2t; b1: k0+8
    #pragma unroll
    for (int i = 0; i < 8; ++i) {
        const int idx = tid + i * 256;          // 0..2047
        const int l   = idx & 31;
        const int p   = (idx >> 5) & 1;
        const int nwi = (idx >> 6) & 1;
        const int w   = idx >> 7;
        const int gg  = l >> 2, tt = l & 3;
        const int k0  = w * 16 + 2 * tt;
        const int n0  = nwi * 32 + 2 * p * 8 + gg;
        uint4 v;
        v.x = pkh2(W1[k0 * NDIM + n0],       W1[(k0 + 1) * NDIM + n0]);
        v.y = pkh2(W1[(k0 + 8) * NDIM + n0], W1[(k0 + 9) * NDIM + n0]);
        v.z = pkh2(W1[k0 * NDIM + n0 + 8],       W1[(k0 + 1) * NDIM + n0 + 8]);
        v.w = pkh2(W1[(k0 + 8) * NDIM + n0 + 8], W1[(k0 + 9) * NDIM + n0 + 8]);
        *(uint4*)(sm + B_OFF + idx * 16) = v;
    }

    // ---- epilogue constants: frag f -> cols j0 = nw*32 + f*8 + 2t, j0+1 ----
    float b1a[4], w2a[4], b1b[4], w2b[4];
    #pragma unroll
    for (int f = 0; f < 4; ++f) {
        const int j0 = nw * 32 + f * 8 + 2 * t;
        b1a[f] = b1[j0];     w2a[f] = W2[j0];
        b1b[f] = b1[j0 + 1]; w2b[f] = W2[j0 + 1];
    }
    const float bb = b2[0];

    const unsigned a_u32 = sm2u32(sm);
    const unsigned b_u32 = sm2u32(sm + B_OFF);

    // ldmatrix lane pointer: r = row, h = k-half; unit u = 2w+h, swizzled u^(r&7)
    const int r   = mw * 16 + (lane & 7) + ((lane >> 3) & 1) * 8;
    const int h   = lane >> 4;
    const int rx7 = r & 7;
    const unsigned abase = a_u32 + r * A_ROW_B;
    const unsigned bbase = b_u32 + lane * 16;

    // gather mapping: e = tid&63, s = tid>>6 (slab of 64 k)
    const int ge_e = tid & 63;
    const int gs   = tid >> 6;
    const unsigned gdst = a_u32 + ge_e * A_ROW_B;
    const int gux = ge_e & 7;                    // swizzle key for stores

    const int ntile_grid = gridDim.x;
    for (int tile = blockIdx.x; tile < ntiles; tile += ntile_grid) {
        // ---- gather + fp16 convert: 64 floats/thread -> 32 halves... (4 chunks) ----
        {
            int ge = tile * TILE_E + ge_e;
            if (ge >= E) ge = E - 1;             // duplicate tail; output guarded
            long long node;
            const long long col = (long long)(gs >> 1) * E + ge;  // src half / dst half
            if (is32) node = ((const int*)edge_index)[col];
            else      node = ((const long long*)edge_index)[col];
            if (node < 0) node = 0;
            if (node >= n_nodes) node = n_nodes - 1;
            const float4* p4 = (const float4*)(node_emb + node * 128 + (gs & 1) * 64);
            #pragma unroll
            for (int c = 0; c < 4; ++c) {
                const float4 v0 = p4[c * 4 + 0];
                const float4 v1 = p4[c * 4 + 1];
                const float4 v2 = p4[c * 4 + 2];
                const float4 v3 = p4[c * 4 + 3];
                uint4 o0, o1;
                o0.x = pkh2(v0.x, v0.y); o0.y = pkh2(v0.z, v0.w);
                o0.z = pkh2(v1.x, v1.y); o0.w = pkh2(v1.z, v1.w);
                o1.x = pkh2(v2.x, v2.y); o1.y = pkh2(v2.z, v2.w);
                o1.z = pkh2(v3.x, v3.y); o1.w = pkh2(v3.z, v3.w);
                const int u0 = gs * 8 + c * 2;
                *(uint4*)(sm + ge_e * A_ROW_B + ((u0 ^ gux) << 4))       = o0;
                *(uint4*)(sm + ge_e * A_ROW_B + (((u0 + 1) ^ gux) << 4)) = o1;
            }
        }
        __syncthreads();

        // ---- GEMM: warp m16 x n32, 16 k16-windows ----
        float acc[4][4];
        #pragma unroll
        for (int f = 0; f < 4; ++f)
            #pragma unroll
            for (int c = 0; c < 4; ++c) acc[f][c] = 0.f;

        #pragma unroll 4
        for (int w = 0; w < 16; ++w) {
            unsigned a0, a1, a2, a3;
            ldm_x4(a0, a1, a2, a3, abase + ((((w << 1) | h) ^ rx7) << 4));
            const uint4 B0 = *(const uint4*)(sm + B_OFF - b_u32 + bbase - a_u32 + 0); // placeholder avoided below
            (void)B0;
            const uint4 Bx = *(const uint4*)(sm + B_OFF + (((w * 2 + nw) * 2 + 0) * 512) + lane * 16);
            const uint4 By = *(const uint4*)(sm + B_OFF + (((w * 2 + nw) * 2 + 1) * 512) + lane * 16);
            mma16816(acc[0], a0, a1, a2, a3, Bx.x, Bx.y);
            mma16816(acc[1], a0, a1, a2, a3, Bx.z, Bx.w);
            mma16816(acc[2], a0, a1, a2, a3, By.x, By.y);
            mma16816(acc[3], a0, a1, a2, a3, By.z, By.w);
        }

        // ---- epilogue: relu(+b1) . W2, reduce t-lanes, combine 2 n-warps ----
        float pg = 0.f, pg8 = 0.f;
        #pragma unroll
        for (int f = 0; f < 4; ++f) {
            pg  = fmaf(fmaxf(acc[f][0] + b1a[f], 0.f), w2a[f], pg);
            pg  = fmaf(fmaxf(acc[f][1] + b1b[f], 0.f), w2b[f], pg);
            pg8 = fmaf(fmaxf(acc[f][2] + b1a[f], 0.f), w2a[f], pg8);
            pg8 = fmaf(fmaxf(acc[f][3] + b1b[f], 0.f), w2b[f], pg8);
        }
        pg  += __shfl_xor_sync(0xffffffffu, pg, 1);
        pg  += __shfl_xor_sync(0xffffffffu, pg, 2);
        pg8 += __shfl_xor_sync(0xffffffffu, pg8, 1);
        pg8 += __shfl_xor_sync(0xffffffffu, pg8, 2);
        if (t == 0) {
            sPart[nw][mw * 16 + g]     = pg;
            sPart[nw][mw * 16 + g + 8] = pg8;
        }
        __syncthreads();
        if (tid < TILE_E) {
            const int e = tile * TILE_E + tid;
            if (e < E) out[e] = sPart[0][tid] + sPart[1][tid] + bb;
        }
        __syncthreads();   // sPart consumed + A reads done before next gather
    }
}

extern "C" void kernel_launch(void* const* d_in, const int* in_sizes, int n_in,
                              void* d_out, int out_size)
{
    const float* node_emb   = (const float*)d_in[0];
    const void*  edge_index = d_in[1];
    const float* W1         = (const float*)d_in[2];
    const float* b1         = (const float*)d_in[3];
    const float* W2         = (const float*)d_in[4];
    const float* b2         = (const float*)d_in[5];
    float*       out        = (float*)d_out;

    const int E       = out_size;
    const int n_nodes = in_sizes[0] / 128;
    const int ntiles  = (E + TILE_E - 1) / TILE_E;   // 12500

    probe_idx_dtype<<<1, 32>>>((const int*)edge_index, 2 * E);

    int nsm = 148;
    cudaDeviceGetAttribute(&nsm, cudaDevAttrMultiProcessorCount, 0);
    int grid = 3 * nsm;
    if (grid > ntiles) grid = ntiles;

    cudaFuncSetAttribute(edge_mlp_h16,
                         cudaFuncAttributeMaxDynamicSharedMemorySize, SMEM_TOTAL);

    edge_mlp_h16<<<grid, THREADS, SMEM_TOTAL>>>(node_emb, edge_index, W1, b1, W2, b2,
                                                out, E, n_nodes, ntiles);
}

// round 9
// speedup vs baseline: 1.3662x; 1.0919x over previous
#include <cuda_runtime.h>
#include <cuda_fp16.h>
#include <cstdint>

#define TILE_E    128
#define KDIM      256
#define NDIM      64
#define THREADS   256
#define A_ROW_B   512                   // 256 halves per edge row
#define A_BYTES   (TILE_E * A_ROW_B)    // 65536
#define B_OFF     A_BYTES
#define B_BYTES   32768
#define SMEM_TOTAL (A_BYTES + B_BYTES)  // 98304 -> 2 CTAs/SM

__device__ int g_idx_is32;   // 1 if edge_index is int32, 0 if int64

__device__ __forceinline__ unsigned sm2u32(const void* p) {
    unsigned a;
    asm("{ .reg .u64 t; cvta.to.shared.u64 t, %1; cvt.u32.u64 %0, t; }" : "=r"(a) : "l"(p));
    return a;
}
__device__ __forceinline__ unsigned pkh2(float a, float b) {   // lo=a, hi=b
    __half2 h = __floats2half2_rn(a, b);
    return *(unsigned*)&h;
}
__device__ __forceinline__ void ldm_x4(unsigned& a0, unsigned& a1, unsigned& a2,
                                       unsigned& a3, unsigned addr) {
    asm volatile("ldmatrix.sync.aligned.m8n8.x4.shared.b16 {%0,%1,%2,%3}, [%4];"
                 : "=r"(a0), "=r"(a1), "=r"(a2), "=r"(a3) : "r"(addr));
}
__device__ __forceinline__ void mma16816(float* c, unsigned a0, unsigned a1,
                                         unsigned a2, unsigned a3,
                                         unsigned b0, unsigned b1) {
    asm volatile(
        "mma.sync.aligned.m16n8k16.row.col.f32.f16.f16.f32 "
        "{%0,%1,%2,%3}, {%4,%5,%6,%7}, {%8,%9}, {%0,%1,%2,%3};"
        : "+f"(c[0]), "+f"(c[1]), "+f"(c[2]), "+f"(c[3])
        : "r"(a0), "r"(a1), "r"(a2), "r"(a3), "r"(b0), "r"(b1));
}

// Probe: int64 ids < 2^31 have zero odd 32-bit words; int32 data has node ids there.
__global__ void probe_idx_dtype(const int* __restrict__ w, int n_words) {
    int any = 0;
    for (int i = threadIdx.x * 2 + 1; i < n_words && i < 8192; i += 64) any |= w[i];
    any = __any_sync(0xffffffffu, any != 0);
    if (threadIdx.x == 0) g_idx_is32 = any ? 1 : 0;
}

__global__ __launch_bounds__(THREADS, 2)
void edge_mlp_h32(const float* __restrict__ node_emb,
                  const void*  __restrict__ edge_index,
                  const float* __restrict__ W1,
                  const float* __restrict__ b1,
                  const float* __restrict__ W2,
                  const float* __restrict__ b2,
                  float* __restrict__ out,
                  int E, int n_nodes, int ntiles)
{
    extern __shared__ unsigned char sm[];
    __shared__ float sPart[2][TILE_E];

    const int tid  = threadIdx.x;
    const int wid  = tid >> 5;
    const int lane = tid & 31;
    const int mw   = wid & 3;        // m-warp: edges mw*32..+31
    const int nw   = wid >> 2;       // n-warp: cols  nw*32..+31
    const int g    = lane >> 2;
    const int t    = lane & 3;
    const int is32 = g_idx_is32;

    // ---- stage B = W1 as fp16 m16n8k16 fragments (once) — layout validated in R8 ----
    // idx=(w, nwi, p, lane): uint4 = frags 2p,2p+1: (b0,b1, b0',b1')
    #pragma unroll
    for (int i = 0; i < 8; ++i) {
        const int idx = tid + i * 256;          // 0..2047
        const int l   = idx & 31;
        const int p   = (idx >> 5) & 1;
        const int nwi = (idx >> 6) & 1;
        const int w   = idx >> 7;
        const int gg  = l >> 2, tt = l & 3;
        const int k0  = w * 16 + 2 * tt;
        const int n0  = nwi * 32 + 2 * p * 8 + gg;
        uint4 v;
        v.x = pkh2(W1[k0 * NDIM + n0],       W1[(k0 + 1) * NDIM + n0]);
        v.y = pkh2(W1[(k0 + 8) * NDIM + n0], W1[(k0 + 9) * NDIM + n0]);
        v.z = pkh2(W1[k0 * NDIM + n0 + 8],       W1[(k0 + 1) * NDIM + n0 + 8]);
        v.w = pkh2(W1[(k0 + 8) * NDIM + n0 + 8], W1[(k0 + 9) * NDIM + n0 + 8]);
        *(uint4*)(sm + B_OFF + idx * 16) = v;
    }

    // ---- epilogue constants: frag f -> cols j0 = nw*32 + f*8 + 2t, j0+1 ----
    float b1a[4], w2a[4], b1b[4], w2b[4];
    #pragma unroll
    for (int f = 0; f < 4; ++f) {
        const int j0 = nw * 32 + f * 8 + 2 * t;
        b1a[f] = b1[j0];     w2a[f] = W2[j0];
        b1b[f] = b1[j0 + 1]; w2b[f] = W2[j0 + 1];
    }
    const float bb = b2[0];

    const unsigned a_u32 = sm2u32(sm);

    // ldmatrix lane pointer: within-m16 row r, k-half h; unit (2w+h)^(row&7)
    const int r   = (lane & 7) + ((lane >> 3) & 1) * 8;   // 0..15
    const int h   = lane >> 4;
    const int r0  = mw * 32 + r;
    const int key = r0 & 7;                                // (r0+16)&7 identical
    const unsigned abase0 = a_u32 + r0 * A_ROW_B;
    const unsigned abase1 = abase0 + 16 * A_ROW_B;

    // gather mapping: 512 tasks = 128 edges x 4 slabs(64 floats); 2 tasks/thread
    const int g_s  = tid & 3;                // slab: 0,1 = src halves; 2,3 = dst halves
    const int g_e0 = tid >> 2;               // edges g_e0 and g_e0+64

    for (int tile = blockIdx.x; tile < ntiles; tile += gridDim.x) {
        // ---- gather + fp16 convert, conflict-free swizzled STS ----
        #pragma unroll
        for (int halfT = 0; halfT < 2; ++halfT) {
            const int e = g_e0 + halfT * 64;
            int ge = tile * TILE_E + e;
            if (ge >= E) ge = E - 1;         // duplicate tail; output guarded
            long long node;
            const long long col = (long long)(g_s >> 1) * E + ge;
            if (is32) node = ((const int*)edge_index)[col];
            else      node = ((const long long*)edge_index)[col];
            if (node < 0) node = 0;
            if (node >= n_nodes) node = n_nodes - 1;
            const float4* p4 = (const float4*)(node_emb + node * 128 + (g_s & 1) * 64);
            unsigned char* rowp = sm + e * A_ROW_B;
            const int ekey = e & 7;
            #pragma unroll
            for (int c = 0; c < 4; ++c) {
                const float4 v0 = p4[c * 4 + 0];
                const float4 v1 = p4[c * 4 + 1];
                const float4 v2 = p4[c * 4 + 2];
                const float4 v3 = p4[c * 4 + 3];
                uint4 o0, o1;
                o0.x = pkh2(v0.x, v0.y); o0.y = pkh2(v0.z, v0.w);
                o0.z = pkh2(v1.x, v1.y); o0.w = pkh2(v1.z, v1.w);
                o1.x = pkh2(v2.x, v2.y); o1.y = pkh2(v2.z, v2.w);
                o1.z = pkh2(v3.x, v3.y); o1.w = pkh2(v3.z, v3.w);
                const int u0 = g_s * 8 + c * 2;
                *(uint4*)(rowp + ((u0 ^ ekey) << 4))       = o0;
                *(uint4*)(rowp + (((u0 + 1) ^ ekey) << 4)) = o1;
            }
        }
        __syncthreads();

        // ---- GEMM: warp m32 x n32, 16 k16-windows, B frags reused for both m16 ----
        float acc0[4][4], acc1[4][4];
        #pragma unroll
        for (int f = 0; f < 4; ++f)
            #pragma unroll
            for (int c = 0; c < 4; ++c) { acc0[f][c] = 0.f; acc1[f][c] = 0.f; }

        #pragma unroll 4
        for (int w = 0; w < 16; ++w) {
            const unsigned uoff = (unsigned)((((w << 1) | h) ^ key) << 4);
            unsigned a0, a1, a2, a3, c0, c1, c2, c3;
            ldm_x4(a0, a1, a2, a3, abase0 + uoff);
            ldm_x4(c0, c1, c2, c3, abase1 + uoff);
            const uint4 Bx = *(const uint4*)(sm + B_OFF + (((w * 2 + nw) * 2 + 0) * 512) + lane * 16);
            const uint4 By = *(const uint4*)(sm + B_OFF + (((w * 2 + nw) * 2 + 1) * 512) + lane * 16);
            mma16816(acc0[0], a0, a1, a2, a3, Bx.x, Bx.y);
            mma16816(acc0[1], a0, a1, a2, a3, Bx.z, Bx.w);
            mma16816(acc0[2], a0, a1, a2, a3, By.x, By.y);
            mma16816(acc0[3], a0, a1, a2, a3, By.z, By.w);
            mma16816(acc1[0], c0, c1, c2, c3, Bx.x, Bx.y);
            mma16816(acc1[1], c0, c1, c2, c3, Bx.z, Bx.w);
            mma16816(acc1[2], c0, c1, c2, c3, By.x, By.y);
            mma16816(acc1[3], c0, c1, c2, c3, By.z, By.w);
        }

        // ---- epilogue: relu(+b1) . W2, reduce t-lanes, combine 2 n-warps ----
        #pragma unroll
        for (int u = 0; u < 2; ++u) {
            float (*acc)[4] = u ? acc1 : acc0;
            float pg = 0.f, pg8 = 0.f;
            #pragma unroll
            for (int f = 0; f < 4; ++f) {
                pg  = fmaf(fmaxf(acc[f][0] + b1a[f], 0.f), w2a[f], pg);
                pg  = fmaf(fmaxf(acc[f][1] + b1b[f], 0.f), w2b[f], pg);
                pg8 = fmaf(fmaxf(acc[f][2] + b1a[f], 0.f), w2a[f], pg8);
                pg8 = fmaf(fmaxf(acc[f][3] + b1b[f], 0.f), w2b[f], pg8);
            }
            pg  += __shfl_xor_sync(0xffffffffu, pg, 1);
            pg  += __shfl_xor_sync(0xffffffffu, pg, 2);
            pg8 += __shfl_xor_sync(0xffffffffu, pg8, 1);
            pg8 += __shfl_xor_sync(0xffffffffu, pg8, 2);
            if (t == 0) {
                sPart[nw][mw * 32 + u * 16 + g]     = pg;
                sPart[nw][mw * 32 + u * 16 + g + 8] = pg8;
            }
        }
        __syncthreads();
        if (tid < TILE_E) {
            const int e = tile * TILE_E + tid;
            if (e < E) out[e] = sPart[0][tid] + sPart[1][tid] + bb;
        }
        __syncthreads();   // sPart consumed + A reads done before next gather
    }
}

extern "C" void kernel_launch(void* const* d_in, const int* in_sizes, int n_in,
                              void* d_out, int out_size)
{
    const float* node_emb   = (const float*)d_in[0];
    const void*  edge_index = d_in[1];
    const float* W1         = (const float*)d_in[2];
    const float* b1         = (const float*)d_in[3];
    const float* W2         = (const float*)d_in[4];
    const float* b2         = (const float*)d_in[5];
    float*       out        = (float*)d_out;

    const int E       = out_size;
    const int n_nodes = in_sizes[0] / 128;
    const int ntiles  = (E + TILE_E - 1) / TILE_E;   // 6250

    probe_idx_dtype<<<1, 32>>>((const int*)edge_index, 2 * E);

    int nsm = 148;
    cudaDeviceGetAttribute(&nsm, cudaDevAttrMultiProcessorCount, 0);
    int grid = 2 * nsm;
    if (grid > ntiles) grid = ntiles;

    cudaFuncSetAttribute(edge_mlp_h32,
                         cudaFuncAttributeMaxDynamicSharedMemorySize, SMEM_TOTAL);

    edge_mlp_h32<<<grid, THREADS, SMEM_TOTAL>>>(node_emb, edge_index, W1, b1, W2, b2,
                                                out, E, n_nodes, ntiles);
}

// round 11
// speedup vs baseline: 2.7525x; 2.0147x over previous
#include <cuda_runtime.h>
#include <cuda_fp16.h>
#include <cstdint>

#define TILE_E    128
#define KDIM      256
#define NDIM      64
#define THREADS   256
#define A_ROW_B   512                   // 256 halves per edge row
#define A_BYTES   (TILE_E * A_ROW_B)    // 65536
#define B_OFF     A_BYTES
#define B_BYTES   32768
#define SMEM_TOTAL (A_BYTES + B_BYTES)  // 98304 -> 2 CTAs/SM

__device__ int g_idx_is32;   // 1 if edge_index is int32, 0 if int64

// 4-bit bidirectional swizzle key (store == ldmatrix-read)
__device__ __forceinline__ int swzkey(int e) {
    return ((e & 3) << 2) | ((e >> 2) & 3);
}
__device__ __forceinline__ unsigned sm2u32(const void* p) {
    unsigned a;
    asm("{ .reg .u64 t; cvta.to.shared.u64 t, %1; cvt.u32.u64 %0, t; }" : "=r"(a) : "l"(p));
    return a;
}
__device__ __forceinline__ unsigned pkh2(float a, float b) {   // lo=a, hi=b
    __half2 h = __floats2half2_rn(a, b);
    return *(unsigned*)&h;
}
__device__ __forceinline__ void ldm_x4(unsigned& a0, unsigned& a1, unsigned& a2,
                                       unsigned& a3, unsigned addr) {
    asm volatile("ldmatrix.sync.aligned.m8n8.x4.shared.b16 {%0,%1,%2,%3}, [%4];"
                 : "=r"(a0), "=r"(a1), "=r"(a2), "=r"(a3) : "r"(addr));
}
__device__ __forceinline__ void mma16816(float* c, unsigned a0, unsigned a1,
                                         unsigned a2, unsigned a3,
                                         unsigned b0, unsigned b1) {
    asm volatile(
        "mma.sync.aligned.m16n8k16.row.col.f32.f16.f16.f32 "
        "{%0,%1,%2,%3}, {%4,%5,%6,%7}, {%8,%9}, {%0,%1,%2,%3};"
        : "+f"(c[0]), "+f"(c[1]), "+f"(c[2]), "+f"(c[3])
        : "r"(a0), "r"(a1), "r"(a2), "r"(a3), "r"(b0), "r"(b1));
}

// Probe: int64 ids < 2^31 have zero odd 32-bit words; int32 data has node ids there.
__global__ void probe_idx_dtype(const int* __restrict__ w, int n_words) {
    int any = 0;
    for (int i = threadIdx.x * 2 + 1; i < n_words && i < 8192; i += 64) any |= w[i];
    any = __any_sync(0xffffffffu, any != 0);
    if (threadIdx.x == 0) g_idx_is32 = any ? 1 : 0;
}

__global__ __launch_bounds__(THREADS, 2)
void edge_mlp_h32c(const float* __restrict__ node_emb,
                   const void*  __restrict__ edge_index,
                   const float* __restrict__ W1,
                   const float* __restrict__ b1,
                   const float* __restrict__ W2,
                   const float* __restrict__ b2,
                   float* __restrict__ out,
                   int E, int n_nodes, int ntiles)
{
    extern __shared__ unsigned char sm[];
    __shared__ int   sNode[2 * TILE_E];
    __shared__ float sPart[2][TILE_E];

    const int tid  = threadIdx.x;
    const int wid  = tid >> 5;
    const int lane = tid & 31;
    const int mw   = wid & 3;        // m-warp: edges mw*32..+31
    const int nw   = wid >> 2;       // n-warp: cols  nw*32..+31
    const int g    = lane >> 2;
    const int t    = lane & 3;
    const int is32 = g_idx_is32;

    // ---- stage B = W1 as fp16 m16n8k16 fragments (once) — layout validated R8/R9 ----
    #pragma unroll
    for (int i = 0; i < 8; ++i) {
        const int idx = tid + i * 256;          // 0..2047
        const int l   = idx & 31;
        const int p   = (idx >> 5) & 1;
        const int nwi = (idx >> 6) & 1;
        const int w   = idx >> 7;
        const int gg  = l >> 2, tt = l & 3;
        const int k0  = w * 16 + 2 * tt;
        const int n0  = nwi * 32 + 2 * p * 8 + gg;
        uint4 v;
        v.x = pkh2(W1[k0 * NDIM + n0],       W1[(k0 + 1) * NDIM + n0]);
        v.y = pkh2(W1[(k0 + 8) * NDIM + n0], W1[(k0 + 9) * NDIM + n0]);
        v.z = pkh2(W1[k0 * NDIM + n0 + 8],       W1[(k0 + 1) * NDIM + n0 + 8]);
        v.w = pkh2(W1[(k0 + 8) * NDIM + n0 + 8], W1[(k0 + 9) * NDIM + n0 + 8]);
        *(uint4*)(sm + B_OFF + idx * 16) = v;
    }

    // ---- epilogue constants: frag f -> cols j0 = nw*32 + f*8 + 2t, j0+1 ----
    float b1a[4], w2a[4], b1b[4], w2b[4];
    #pragma unroll
    for (int f = 0; f < 4; ++f) {
        const int j0 = nw * 32 + f * 8 + 2 * t;
        b1a[f] = b1[j0];     w2a[f] = W2[j0];
        b1b[f] = b1[j0 + 1]; w2b[f] = W2[j0 + 1];
    }
    const float bb = b2[0];

    const unsigned a_u32 = sm2u32(sm);

    // ldmatrix lane pointer: within-m16 row + k-half; unit ((w<<1)|h) ^ swzkey(row)
    const int r_local = (lane & 7) | (((lane >> 3) & 1) << 3);   // 0..15
    const int h       = lane >> 4;
    const int lkey    = swzkey(r_local);      // invariant under +16 and +mw*32
    const unsigned abase0 = a_u32 + (mw * 32 + r_local) * A_ROW_B;
    const unsigned abase1 = abase0 + 16 * A_ROW_B;

    // gather lane mapping: 8 lanes per node-row
    const int gs = tid & 7;                   // lane-in-row
    const int gG = tid >> 3;                  // row-group 0..31

    for (int tile = blockIdx.x; tile < ntiles; tile += gridDim.x) {
        // ---- stage edge ids (rows 0..127 = src, 128..255 = dst) ----
        {
            const int e = tid & 127;
            const int H = tid >> 7;
            int ge = tile * TILE_E + e;
            if (ge >= E) ge = E - 1;          // duplicate tail; output guarded
            long long node;
            const long long col = (long long)H * E + ge;
            if (is32) node = ((const int*)edge_index)[col];
            else      node = ((const long long*)edge_index)[col];
            if (node < 0) node = 0;
            if (node >= n_nodes) node = n_nodes - 1;
            sNode[tid] = (int)node;
        }
        __syncthreads();

        // ---- gather + fp16 convert: 8 passes, 8 lanes/row, coalesced LDG ----
        #pragma unroll
        for (int p = 0; p < 8; ++p) {
            const int row = p * 32 + gG;
            const int e   = row & 127;
            const int H   = row >> 7;
            const int node = sNode[row];
            const float4* src = (const float4*)(node_emb + (long long)node * 128) + gs;
            unsigned char* rowp = sm + e * A_ROW_B;
            const int ekey = swzkey(e);
            #pragma unroll
            for (int q = 0; q < 4; ++q) {
                const float4 v = src[q * 8];           // floats q*32 + gs*4, 128B/row/instr
                uint2 o;
                o.x = pkh2(v.x, v.y);
                o.y = pkh2(v.z, v.w);
                const int unit = H * 16 + q * 4 + (gs >> 1);
                *(uint2*)(rowp + ((unit ^ ekey) << 4) + (gs & 1) * 8) = o;
            }
        }
        __syncthreads();

        // ---- GEMM: warp m32 x n32, 16 k16-windows, B frags reused for both m16 ----
        float acc0[4][4], acc1[4][4];
        #pragma unroll
        for (int f = 0; f < 4; ++f)
            #pragma unroll
            for (int c = 0; c < 4; ++c) { acc0[f][c] = 0.f; acc1[f][c] = 0.f; }

        #pragma unroll 4
        for (int w = 0; w < 16; ++w) {
            const unsigned uoff = (unsigned)((((w << 1) | h) ^ lkey) << 4);
            unsigned a0, a1, a2, a3, c0, c1, c2, c3;
            ldm_x4(a0, a1, a2, a3, abase0 + uoff);
            ldm_x4(c0, c1, c2, c3, abase1 + uoff);
            const uint4 Bx = *(const uint4*)(sm + B_OFF + (((w * 2 + nw) * 2 + 0) * 512) + lane * 16);
            const uint4 By = *(const uint4*)(sm + B_OFF + (((w * 2 + nw) * 2 + 1) * 512) + lane * 16);
            mma16816(acc0[0], a0, a1, a2, a3, Bx.x, Bx.y);
            mma16816(acc0[1], a0, a1, a2, a3, Bx.z, Bx.w);
            mma16816(acc0[2], a0, a1, a2, a3, By.x, By.y);
            mma16816(acc0[3], a0, a1, a2, a3, By.z, By.w);
            mma16816(acc1[0], c0, c1, c2, c3, Bx.x, Bx.y);
            mma16816(acc1[1], c0, c1, c2, c3, Bx.z, Bx.w);
            mma16816(acc1[2], c0, c1, c2, c3, By.x, By.y);
            mma16816(acc1[3], c0, c1, c2, c3, By.z, By.w);
        }

        // ---- epilogue: relu(+b1) . W2, reduce t-lanes, combine 2 n-warps ----
        #pragma unroll
        for (int u = 0; u < 2; ++u) {
            float (*acc)[4] = u ? acc1 : acc0;
            float pg = 0.f, pg8 = 0.f;
            #pragma unroll
            for (int f = 0; f < 4; ++f) {
                pg  = fmaf(fmaxf(acc[f][0] + b1a[f], 0.f), w2a[f], pg);
                pg  = fmaf(fmaxf(acc[f][1] + b1b[f], 0.f), w2b[f], pg);
                pg8 = fmaf(fmaxf(acc[f][2] + b1a[f], 0.f), w2a[f], pg8);
                pg8 = fmaf(fmaxf(acc[f][3] + b1b[f], 0.f), w2b[f], pg8);
            }
            pg  += __shfl_xor_sync(0xffffffffu, pg, 1);
            pg  += __shfl_xor_sync(0xffffffffu, pg, 2);
            pg8 += __shfl_xor_sync(0xffffffffu, pg8, 1);
            pg8 += __shfl_xor_sync(0xffffffffu, pg8, 2);
            if (t == 0) {
                sPart[nw][mw * 32 + u * 16 + g]     = pg;
                sPart[nw][mw * 32 + u * 16 + g + 8] = pg8;
            }
        }
        __syncthreads();
        if (tid < TILE_E) {
            const int e = tile * TILE_E + tid;
            if (e < E) out[e] = sPart[0][tid] + sPart[1][tid] + bb;
        }
        __syncthreads();   // sPart + A reads done before next gather overwrites
    }
}

extern "C" void kernel_launch(void* const* d_in, const int* in_sizes, int n_in,
                              void* d_out, int out_size)
{
    const float* node_emb   = (const float*)d_in[0];
    const void*  edge_index = d_in[1];
    const float* W1         = (const float*)d_in[2];
    const float* b1         = (const float*)d_in[3];
    const float* W2         = (const float*)d_in[4];
    const float* b2         = (const float*)d_in[5];
    float*       out        = (float*)d_out;

    const int E       = out_size;
    const int n_nodes = in_sizes[0] / 128;
    const int ntiles  = (E + TILE_E - 1) / TILE_E;   // 6250

    probe_idx_dtype<<<1, 32>>>((const int*)edge_index, 2 * E);

    int nsm = 148;
    cudaDeviceGetAttribute(&nsm, cudaDevAttrMultiProcessorCount, 0);
    int grid = 2 * nsm;
    if (grid > ntiles) grid = ntiles;

    cudaFuncSetAttribute(edge_mlp_h32c,
                         cudaFuncAttributeMaxDynamicSharedMemorySize, SMEM_TOTAL);

    edge_mlp_h32c<<<grid, THREADS, SMEM_TOTAL>>>(node_emb, edge_index, W1, b1, W2, b2,
                                                 out, E, n_nodes, ntiles);
}

// round 12
// speedup vs baseline: 2.7955x; 1.0156x over previous
#include <cuda_runtime.h>
#include <cuda_fp16.h>
#include <cstdint>

#define TILE_E    128
#define KDIM      256
#define NDIM      64
#define THREADS   512
#define A_ROW_B   512                   // 256 halves per edge row
#define A_BYTES   (TILE_E * A_ROW_B)    // 65536
#define B_OFF     (2 * A_BYTES)         // 131072
#define B_BYTES   32768
#define SMEM_TOTAL (B_OFF + B_BYTES)    // 163840 -> 1 CTA/SM, 16 warps

__device__ int g_idx_is32;   // 1 if edge_index is int32, 0 if int64

// 4-bit bidirectional swizzle key (store == ldmatrix-read); validated R10
__device__ __forceinline__ int swzkey(int e) {
    return ((e & 3) << 2) | ((e >> 2) & 3);
}
__device__ __forceinline__ unsigned sm2u32(const void* p) {
    unsigned a;
    asm("{ .reg .u64 t; cvta.to.shared.u64 t, %1; cvt.u32.u64 %0, t; }" : "=r"(a) : "l"(p));
    return a;
}
__device__ __forceinline__ unsigned pkh2(float a, float b) {
    __half2 h = __floats2half2_rn(a, b);
    return *(unsigned*)&h;
}
__device__ __forceinline__ void ldm_x4(unsigned& a0, unsigned& a1, unsigned& a2,
                                       unsigned& a3, unsigned addr) {
    asm volatile("ldmatrix.sync.aligned.m8n8.x4.shared.b16 {%0,%1,%2,%3}, [%4];"
                 : "=r"(a0), "=r"(a1), "=r"(a2), "=r"(a3) : "r"(addr));
}
__device__ __forceinline__ void mma16816(float* c, unsigned a0, unsigned a1,
                                         unsigned a2, unsigned a3,
                                         unsigned b0, unsigned b1) {
    asm volatile(
        "mma.sync.aligned.m16n8k16.row.col.f32.f16.f16.f32 "
        "{%0,%1,%2,%3}, {%4,%5,%6,%7}, {%8,%9}, {%0,%1,%2,%3};"
        : "+f"(c[0]), "+f"(c[1]), "+f"(c[2]), "+f"(c[3])
        : "r"(a0), "r"(a1), "r"(a2), "r"(a3), "r"(b0), "r"(b1));
}

// Probe: int64 ids < 2^31 have zero odd 32-bit words; int32 data has node ids there.
__global__ void probe_idx_dtype(const int* __restrict__ w, int n_words) {
    int any = 0;
    for (int i = threadIdx.x * 2 + 1; i < n_words && i < 8192; i += 64) any |= w[i];
    any = __any_sync(0xffffffffu, any != 0);
    if (threadIdx.x == 0) g_idx_is32 = any ? 1 : 0;
}

__global__ __launch_bounds__(THREADS, 1)
void edge_mlp_ws(const float* __restrict__ node_emb,
                 const void*  __restrict__ edge_index,
                 const float* __restrict__ W1,
                 const float* __restrict__ b1,
                 const float* __restrict__ W2,
                 const float* __restrict__ b2,
                 float* __restrict__ out,
                 int E, int n_nodes, int ntiles)
{
    extern __shared__ unsigned char sm[];
    __shared__ float sPart[2][TILE_E];

    const int tid  = threadIdx.x;
    const int wid  = tid >> 5;
    const int lane = tid & 31;
    const int is32 = g_idx_is32;
    const bool producer = wid >= 8;

    // ---- stage B = W1 as fp16 m16n8k16 fragments (once, all 512 threads) ----
    #pragma unroll
    for (int i = 0; i < 4; ++i) {
        const int idx = tid + i * 512;          // 0..2047
        const int l   = idx & 31;
        const int p   = (idx >> 5) & 1;
        const int nwi = (idx >> 6) & 1;
        const int w   = idx >> 7;
        const int gg  = l >> 2, tt = l & 3;
        const int k0  = w * 16 + 2 * tt;
        const int n0  = nwi * 32 + 2 * p * 8 + gg;
        uint4 v;
        v.x = pkh2(W1[k0 * NDIM + n0],       W1[(k0 + 1) * NDIM + n0]);
        v.y = pkh2(W1[(k0 + 8) * NDIM + n0], W1[(k0 + 9) * NDIM + n0]);
        v.z = pkh2(W1[k0 * NDIM + n0 + 8],       W1[(k0 + 1) * NDIM + n0 + 8]);
        v.w = pkh2(W1[(k0 + 8) * NDIM + n0 + 8], W1[(k0 + 9) * NDIM + n0 + 8]);
        *(uint4*)(sm + B_OFF + idx * 16) = v;
    }

    // ---- consumer setup (warps 0..7): 4m(m32) x 2n(n32) ----
    const int mw = wid & 3;
    const int nw = (wid >> 2) & 1;
    const int g  = lane >> 2;
    const int t  = lane & 3;
    float b1a[4], w2a[4], b1b[4], w2b[4];
    #pragma unroll
    for (int f = 0; f < 4; ++f) {
        const int j0 = nw * 32 + f * 8 + 2 * t;
        b1a[f] = b1[j0];     w2a[f] = W2[j0];
        b1b[f] = b1[j0 + 1]; w2b[f] = W2[j0 + 1];
    }
    const float bb = b2[0];

    const unsigned a_u32 = sm2u32(sm);
    const int r_local = (lane & 7) | (((lane >> 3) & 1) << 3);   // 0..15
    const int h       = lane >> 4;
    const int lkey    = swzkey(r_local);                          // +16/+32 invariant
    const unsigned aoff0 = (unsigned)((mw * 32 + r_local) * A_ROW_B);

    // ---- producer setup (warps 8..15): 32 rows per warp, 8 lanes/row gather ----
    const int pwid = wid - 8;
    const int gs   = lane & 7;

    const int grid = gridDim.x;
    const int bid  = blockIdx.x;
    const int nloc = (ntiles - bid - 1) / grid + 1;   // tiles for this CTA (bid < ntiles)

    __syncthreads();   // B staged

    for (int it = 0; it <= nloc; ++it) {
        __syncthreads();   // handoff: buffer (it-1)&1 full, buffer it&1 free

        if (producer) {
            if (it < nloc) {
                const int tile = bid + it * grid;
                // coalesced id load: lane l owns row pwid*32+l
                const int rmy = pwid * 32 + lane;
                const int emy = rmy & 127, Hmy = rmy >> 7;
                int ge = tile * TILE_E + emy;
                if (ge >= E) ge = E - 1;               // duplicate tail; output guarded
                long long nd;
                const long long col = (long long)Hmy * E + ge;
                if (is32) nd = ((const int*)edge_index)[col];
                else      nd = ((const long long*)edge_index)[col];
                if (nd < 0) nd = 0;
                if (nd >= n_nodes) nd = n_nodes - 1;
                const int node_my = (int)nd;

                unsigned char* abuf = sm + (it & 1) * A_BYTES;
                #pragma unroll
                for (int p = 0; p < 8; ++p) {
                    const int rr   = pwid * 32 + p * 4 + (lane >> 3);
                    const int node = __shfl_sync(0xffffffffu, node_my, p * 4 + (lane >> 3));
                    const int e2   = rr & 127, H2 = rr >> 7;
                    const float4* src = (const float4*)(node_emb + (long long)node * 128) + gs;
                    unsigned char* rowp = abuf + e2 * A_ROW_B;
                    const int ekey = swzkey(e2);
                    #pragma unroll
                    for (int q = 0; q < 4; ++q) {
                        const float4 v = src[q * 8];   // coalesced: 8 lanes tile the 128B line
                        uint2 o;
                        o.x = pkh2(v.x, v.y);
                        o.y = pkh2(v.z, v.w);
                        const int unit = H2 * 16 + q * 4 + (gs >> 1);
                        *(uint2*)(rowp + ((unit ^ ekey) << 4) + (gs & 1) * 8) = o;
                    }
                }
            }
        } else if (it > 0) {
            const int tile = bid + (it - 1) * grid;
            const unsigned abase0 = a_u32 + (unsigned)(((it - 1) & 1) * A_BYTES) + aoff0;
            const unsigned abase1 = abase0 + 16 * A_ROW_B;
            const unsigned char* bsm = sm + B_OFF;

            float acc0[4][4], acc1[4][4];
            #pragma unroll
            for (int f = 0; f < 4; ++f)
                #pragma unroll
                for (int c = 0; c < 4; ++c) { acc0[f][c] = 0.f; acc1[f][c] = 0.f; }

            #pragma unroll 4
            for (int w = 0; w < 16; ++w) {
                const unsigned uoff = (unsigned)((((w << 1) | h) ^ lkey) << 4);
                unsigned a0, a1, a2, a3, c0, c1, c2, c3;
                ldm_x4(a0, a1, a2, a3, abase0 + uoff);
                ldm_x4(c0, c1, c2, c3, abase1 + uoff);
                const uint4 Bx = *(const uint4*)(bsm + (((w * 2 + nw) * 2 + 0) * 512) + lane * 16);
                const uint4 By = *(const uint4*)(bsm + (((w * 2 + nw) * 2 + 1) * 512) + lane * 16);
                mma16816(acc0[0], a0, a1, a2, a3, Bx.x, Bx.y);
                mma16816(acc0[1], a0, a1, a2, a3, Bx.z, Bx.w);
                mma16816(acc0[2], a0, a1, a2, a3, By.x, By.y);
                mma16816(acc0[3], a0, a1, a2, a3, By.z, By.w);
                mma16816(acc1[0], c0, c1, c2, c3, Bx.x, Bx.y);
                mma16816(acc1[1], c0, c1, c2, c3, Bx.z, Bx.w);
                mma16816(acc1[2], c0, c1, c2, c3, By.x, By.y);
                mma16816(acc1[3], c0, c1, c2, c3, By.z, By.w);
            }

            // epilogue: relu(+b1) . W2, reduce t-lanes, combine 2 n-warps
            #pragma unroll
            for (int u = 0; u < 2; ++u) {
                float (*acc)[4] = u ? acc1 : acc0;
                float pg = 0.f, pg8 = 0.f;
                #pragma unroll
                for (int f = 0; f < 4; ++f) {
                    pg  = fmaf(fmaxf(acc[f][0] + b1a[f], 0.f), w2a[f], pg);
                    pg  = fmaf(fmaxf(acc[f][1] + b1b[f], 0.f), w2b[f], pg);
                    pg8 = fmaf(fmaxf(acc[f][2] + b1a[f], 0.f), w2a[f], pg8);
                    pg8 = fmaf(fmaxf(acc[f][3] + b1b[f], 0.f), w2b[f], pg8);
                }
                pg  += __shfl_xor_sync(0xffffffffu, pg, 1);
                pg  += __shfl_xor_sync(0xffffffffu, pg, 2);
                pg8 += __shfl_xor_sync(0xffffffffu, pg8, 1);
                pg8 += __shfl_xor_sync(0xffffffffu, pg8, 2);
                if (t == 0) {
                    sPart[nw][mw * 32 + u * 16 + g]     = pg;
                    sPart[nw][mw * 32 + u * 16 + g + 8] = pg8;
                }
            }
            asm volatile("bar.sync 1, 256;" ::: "memory");   // consumers only
            if (tid < TILE_E) {
                const int e = tile * TILE_E + tid;
                if (e < E) out[e] = sPart[0][tid] + sPart[1][tid] + bb;
            }
            // next sPart write is after the loop-top __syncthreads -> safe
        }
    }
}

extern "C" void kernel_launch(void* const* d_in, const int* in_sizes, int n_in,
                              void* d_out, int out_size)
{
    const float* node_emb   = (const float*)d_in[0];
    const void*  edge_index = d_in[1];
    const float* W1         = (const float*)d_in[2];
    const float* b1         = (const float*)d_in[3];
    const float* W2         = (const float*)d_in[4];
    const float* b2         = (const float*)d_in[5];
    float*       out        = (float*)d_out;

    const int E       = out_size;
    const int n_nodes = in_sizes[0] / 128;
    const int ntiles  = (E + TILE_E - 1) / TILE_E;   // 6250

    probe_idx_dtype<<<1, 32>>>((const int*)edge_index, 2 * E);

    int nsm = 148;
    cudaDeviceGetAttribute(&nsm, cudaDevAttrMultiProcessorCount, 0);
    int grid = nsm;
    if (grid > ntiles) grid = ntiles;

    cudaFuncSetAttribute(edge_mlp_ws,
                         cudaFuncAttributeMaxDynamicSharedMemorySize, SMEM_TOTAL);

    edge_mlp_ws<<<grid, THREADS, SMEM_TOTAL>>>(node_emb, edge_index, W1, b1, W2, b2,
                                               out, E, n_nodes, ntiles);
}

// round 13
// speedup vs baseline: 3.5189x; 1.2587x over previous
#include <cuda_runtime.h>
#include <cuda_fp16.h>
#include <cstdint>

#define TILE_E    128
#define KDIM      256
#define NDIM      64
#define THREADS   384                   // 4 consumer + 8 producer warps
#define A_ROW_B   512                   // 256 halves per edge row
#define A_BYTES   (TILE_E * A_ROW_B)    // 65536
#define B_OFF     (2 * A_BYTES)         // 131072
#define B_BYTES   32768
#define SMEM_TOTAL (B_OFF + B_BYTES)    // 163840 -> 1 CTA/SM

__device__ int g_idx_is32;   // 1 if edge_index is int32, 0 if int64

// 4-bit bidirectional swizzle key (store == ldmatrix-read); validated R10/R11
__device__ __forceinline__ int swzkey(int e) {
    return ((e & 3) << 2) | ((e >> 2) & 3);
}
__device__ __forceinline__ unsigned sm2u32(const void* p) {
    unsigned a;
    asm("{ .reg .u64 t; cvta.to.shared.u64 t, %1; cvt.u32.u64 %0, t; }" : "=r"(a) : "l"(p));
    return a;
}
__device__ __forceinline__ unsigned pkh2(float a, float b) {
    __half2 h = __floats2half2_rn(a, b);
    return *(unsigned*)&h;
}
__device__ __forceinline__ void ldm_x4(unsigned& a0, unsigned& a1, unsigned& a2,
                                       unsigned& a3, unsigned addr) {
    asm volatile("ldmatrix.sync.aligned.m8n8.x4.shared.b16 {%0,%1,%2,%3}, [%4];"
                 : "=r"(a0), "=r"(a1), "=r"(a2), "=r"(a3) : "r"(addr));
}
__device__ __forceinline__ void mma16816(float* c, unsigned a0, unsigned a1,
                                         unsigned a2, unsigned a3,
                                         unsigned b0, unsigned b1) {
    asm volatile(
        "mma.sync.aligned.m16n8k16.row.col.f32.f16.f16.f32 "
        "{%0,%1,%2,%3}, {%4,%5,%6,%7}, {%8,%9}, {%0,%1,%2,%3};"
        : "+f"(c[0]), "+f"(c[1]), "+f"(c[2]), "+f"(c[3])
        : "r"(a0), "r"(a1), "r"(a2), "r"(a3), "r"(b0), "r"(b1));
}

// Fast probe: 256 threads sample odd 32-bit words; int64 ids < 2^31 -> all zero.
__global__ void probe_idx_dtype(const int* __restrict__ w, int n_words) {
    int any = 0;
    for (int i = threadIdx.x * 2 + 1; i < n_words && i < 8192; i += 512) any |= w[i];
    any = __syncthreads_or(any != 0);
    if (threadIdx.x == 0) g_idx_is32 = any ? 1 : 0;
}

__global__ __launch_bounds__(THREADS, 1)
void edge_mlp_ws2(const float* __restrict__ node_emb,
                  const void*  __restrict__ edge_index,
                  const float* __restrict__ W1,
                  const float* __restrict__ b1,
                  const float* __restrict__ W2,
                  const float* __restrict__ b2,
                  float* __restrict__ out,
                  int E, int n_nodes, int ntiles)
{
    extern __shared__ unsigned char sm[];

    const int tid  = threadIdx.x;
    const int wid  = tid >> 5;
    const int lane = tid & 31;
    const int is32 = g_idx_is32;
    const bool producer = wid >= 4;

    // ---- stage B = W1 as fp16 m16n8k16 fragments (once) — layout validated R8+ ----
    for (int idx = tid; idx < 2048; idx += THREADS) {
        const int l   = idx & 31;
        const int p   = (idx >> 5) & 1;
        const int nwi = (idx >> 6) & 1;
        const int w   = idx >> 7;
        const int gg  = l >> 2, tt = l & 3;
        const int k0  = w * 16 + 2 * tt;
        const int n0  = nwi * 32 + 2 * p * 8 + gg;
        uint4 v;
        v.x = pkh2(W1[k0 * NDIM + n0],       W1[(k0 + 1) * NDIM + n0]);
        v.y = pkh2(W1[(k0 + 8) * NDIM + n0], W1[(k0 + 9) * NDIM + n0]);
        v.z = pkh2(W1[k0 * NDIM + n0 + 8],       W1[(k0 + 1) * NDIM + n0 + 8]);
        v.w = pkh2(W1[(k0 + 8) * NDIM + n0 + 8], W1[(k0 + 9) * NDIM + n0 + 8]);
        *(uint4*)(sm + B_OFF + idx * 16) = v;
    }

    // ---- consumer setup (warps 0..3): warp = m32 x n64 ----
    const int mw = wid & 3;
    const int g  = lane >> 2;
    const int t  = lane & 3;
    // frag fr (0..7) covers cols fr*8 + {2t, 2t+1}
    float b1a[8], w2a[8], b1b[8], w2b[8];
    #pragma unroll
    for (int fr = 0; fr < 8; ++fr) {
        const int j0 = fr * 8 + 2 * t;
        b1a[fr] = b1[j0];     w2a[fr] = W2[j0];
        b1b[fr] = b1[j0 + 1]; w2b[fr] = W2[j0 + 1];
    }
    const float bb = b2[0];

    const unsigned a_u32 = sm2u32(sm);
    const int r_local = (lane & 7) | (((lane >> 3) & 1) << 3);   // 0..15
    const int h       = lane >> 4;
    const int lkey    = swzkey(r_local);                          // +16/+32 invariant
    const unsigned aoff0 = (unsigned)((mw * 32 + r_local) * A_ROW_B);

    // ---- producer setup (warps 4..11): 32 rows/warp, 8 lanes/row coalesced ----
    const int pwid = wid - 4;
    const int gs   = lane & 7;

    const int grid = gridDim.x;
    const int bid  = blockIdx.x;
    const int nloc = (ntiles - bid - 1) / grid + 1;   // tiles for this CTA

    __syncthreads();   // B staged

    for (int it = 0; it <= nloc; ++it) {
        __syncthreads();   // handoff: buffer (it-1)&1 full, buffer it&1 free

        if (producer) {
            if (it < nloc) {
                const int tile = bid + it * grid;
                // coalesced id load: lane l owns row pwid*32+l
                const int rmy = pwid * 32 + lane;
                const int emy = rmy & 127, Hmy = rmy >> 7;
                int ge = tile * TILE_E + emy;
                if (ge >= E) ge = E - 1;               // duplicate tail; output guarded
                long long nd;
                const long long col = (long long)Hmy * E + ge;
                if (is32) nd = ((const int*)edge_index)[col];
                else      nd = ((const long long*)edge_index)[col];
                if (nd < 0) nd = 0;
                if (nd >= n_nodes) nd = n_nodes - 1;
                const int node_my = (int)nd;

                unsigned char* abuf = sm + (it & 1) * A_BYTES;
                #pragma unroll
                for (int p = 0; p < 8; ++p) {
                    const int rr   = pwid * 32 + p * 4 + (lane >> 3);
                    const int node = __shfl_sync(0xffffffffu, node_my, p * 4 + (lane >> 3));
                    const int e2   = rr & 127, H2 = rr >> 7;
                    const float4* src = (const float4*)(node_emb + (long long)node * 128) + gs;
                    unsigned char* rowp = abuf + e2 * A_ROW_B;
                    const int ekey = swzkey(e2);
                    #pragma unroll
                    for (int q = 0; q < 4; ++q) {
                        const float4 v = src[q * 8];   // 8 lanes tile the 128B line
                        uint2 o;
                        o.x = pkh2(v.x, v.y);
                        o.y = pkh2(v.z, v.w);
                        const int unit = H2 * 16 + q * 4 + (gs >> 1);
                        *(uint2*)(rowp + ((unit ^ ekey) << 4) + (gs & 1) * 8) = o;
                    }
                }
            }
        } else if (it > 0) {
            const int tile = bid + (it - 1) * grid;
            const unsigned abase0 = a_u32 + (unsigned)(((it - 1) & 1) * A_BYTES) + aoff0;
            const unsigned abase1 = abase0 + 16 * A_ROW_B;
            const unsigned char* bsm = sm + B_OFF;

            float acc0[8][4], acc1[8][4];
            #pragma unroll
            for (int fr = 0; fr < 8; ++fr)
                #pragma unroll
                for (int c = 0; c < 4; ++c) { acc0[fr][c] = 0.f; acc1[fr][c] = 0.f; }

            #pragma unroll 2
            for (int w = 0; w < 16; ++w) {
                const unsigned uoff = (unsigned)((((w << 1) | h) ^ lkey) << 4);
                unsigned a0, a1, a2, a3, c0, c1, c2, c3;
                ldm_x4(a0, a1, a2, a3, abase0 + uoff);
                ldm_x4(c0, c1, c2, c3, abase1 + uoff);
                #pragma unroll
                for (int nwi = 0; nwi < 2; ++nwi)
                    #pragma unroll
                    for (int p = 0; p < 2; ++p) {
                        const uint4 q = *(const uint4*)(bsm + (((w * 2 + nwi) * 2 + p) * 512) + lane * 16);
                        const int fr = nwi * 4 + 2 * p;
                        mma16816(acc0[fr],     a0, a1, a2, a3, q.x, q.y);
                        mma16816(acc0[fr + 1], a0, a1, a2, a3, q.z, q.w);
                        mma16816(acc1[fr],     c0, c1, c2, c3, q.x, q.y);
                        mma16816(acc1[fr + 1], c0, c1, c2, c3, q.z, q.w);
                    }
            }

            // ---- epilogue: relu(+b1) . W2 over all 64 cols, reduce t-lanes, store ----
            const int ebase = tile * TILE_E + mw * 32;
            #pragma unroll
            for (int u = 0; u < 2; ++u) {
                float (*acc)[4] = u ? acc1 : acc0;
                float pg = 0.f, pg8 = 0.f;
                #pragma unroll
                for (int fr = 0; fr < 8; ++fr) {
                    pg  = fmaf(fmaxf(acc[fr][0] + b1a[fr], 0.f), w2a[fr], pg);
                    pg  = fmaf(fmaxf(acc[fr][1] + b1b[fr], 0.f), w2b[fr], pg);
                    pg8 = fmaf(fmaxf(acc[fr][2] + b1a[fr], 0.f), w2a[fr], pg8);
                    pg8 = fmaf(fmaxf(acc[fr][3] + b1b[fr], 0.f), w2b[fr], pg8);
                }
                pg  += __shfl_xor_sync(0xffffffffu, pg, 1);
                pg  += __shfl_xor_sync(0xffffffffu, pg, 2);
                pg8 += __shfl_xor_sync(0xffffffffu, pg8, 1);
                pg8 += __shfl_xor_sync(0xffffffffu, pg8, 2);
                if (t == 0) {
                    const int e0 = ebase + u * 16 + g;
                    if (e0 < E)     out[e0]     = pg  + bb;
                    if (e0 + 8 < E) out[e0 + 8] = pg8 + bb;
                }
            }
        }
    }
}

extern "C" void kernel_launch(void* const* d_in, const int* in_sizes, int n_in,
                              void* d_out, int out_size)
{
    const float* node_emb   = (const float*)d_in[0];
    const void*  edge_index = d_in[1];
    const float* W1         = (const float*)d_in[2];
    const float* b1         = (const float*)d_in[3];
    const float* W2         = (const float*)d_in[4];
    const float* b2         = (const float*)d_in[5];
    float*       out        = (float*)d_out;

    const int E       = out_size;
    const int n_nodes = in_sizes[0] / 128;
    const int ntiles  = (E + TILE_E - 1) / TILE_E;   // 6250

    probe_idx_dtype<<<1, 256>>>((const int*)edge_index, 2 * E);

    int nsm = 148;
    cudaDeviceGetAttribute(&nsm, cudaDevAttrMultiProcessorCount, 0);
    int grid = nsm;
    if (grid > ntiles) grid = ntiles;

    cudaFuncSetAttribute(edge_mlp_ws2,
                         cudaFuncAttributeMaxDynamicSharedMemorySize, SMEM_TOTAL);

    edge_mlp_ws2<<<grid, THREADS, SMEM_TOTAL>>>(node_emb, edge_index, W1, b1, W2, b2,
                                                out, E, n_nodes, ntiles);
}